// round 12
// baseline (speedup 1.0000x reference)
#include <cuda_runtime.h>
#include <cuda_bf16.h>

// ---------------------------------------------------------------------------
// DMPNN, round 12: all segment sums via CSR GATHER (no float atomics).
// R11 post-mortem: the red.v4 scatters were the binding constraint
// (~51.2M L2 atomic-lanes per segsum x 5). CSR gather does the same sums
// with coalesced loads only.
//   CSR over dst: hist -> block scan -> fill           (once per launch)
//   P   = node @ W1[:128] + b1                         (tiled GEMM)
//   h0  = relu(P[src] + ef @ W1[128:])                 (writes h only)
//   4x: agg = gather(h, csr)                           (k_agg, no atomics)
//       A   = agg @ Wu + bu
//       k_step: mirror tile pair, g = h@Wu in registers,
//               h = relu(A[src] - valid*g[rev] + h)    (writes h only)
//   agg = gather(h); out = relu([node || agg] @ Wf + bf)
// rev(e) = e +- E/2 (validated per-edge).  Scalar FFMA only (f32x2 slower
// on sm_100a).  k_step: 512 thr, 2 blocks/SM (proven R9 win).
// Device-global addresses via cudaGetSymbolAddress ONLY (ATS trap).
// Static-init warmup pre-triggers all lazy driver allocations.
// ---------------------------------------------------------------------------

#define EMAX 800000
#define NMAX 50000

__device__ float g_h[(size_t)EMAX * 64];     // edge hidden state
__device__ float g_agg[(size_t)NMAX * 64];   // segment sums
__device__ float g_A[(size_t)NMAX * 64];     // P, then A per step
__device__ int   g_rowptr[NMAX + 1];
__device__ int   g_deg[NMAX];
__device__ int   g_csr[EMAX];
__device__ int   g_idum[64];                 // warmup scratch

// ---------------------------- CSR construction -----------------------------

__global__ void k_zero_deg(int* __restrict__ deg, int n) {
    int i = blockIdx.x * blockDim.x + threadIdx.x;
    if (i < n) deg[i] = 0;
}

__global__ void k_hist(const int* __restrict__ dst, int* __restrict__ deg, int E) {
    int i = blockIdx.x * blockDim.x + threadIdx.x;
    if (i < E) atomicAdd(&deg[dst[i]], 1);
}

__global__ void k_scan(const int* __restrict__ deg, int* __restrict__ rowptr, int n) {
    __shared__ int s[1024];
    int t = threadIdx.x;
    int carry = 0;
    for (int base = 0; base < n; base += 1024) {
        int v = (base + t < n) ? deg[base + t] : 0;
        s[t] = v;
        __syncthreads();
        for (int off = 1; off < 1024; off <<= 1) {
            int x = (t >= off) ? s[t - off] : 0;
            __syncthreads();
            s[t] += x;
            __syncthreads();
        }
        if (base + t < n) rowptr[base + t] = carry + s[t] - v;
        int total = s[1023];
        carry += total;
        __syncthreads();
    }
    if (t == 0) rowptr[n] = carry;
}

__global__ void k_fill(const int* __restrict__ dst, const int* __restrict__ rowptr,
                       int* __restrict__ cursor, int* __restrict__ csr, int E) {
    int i = blockIdx.x * blockDim.x + threadIdx.x;
    if (i < E) {
        int d = dst[i];
        int pos = rowptr[d] + atomicAdd(&cursor[d], 1);
        csr[pos] = i;
    }
}

// ------------------------- segment sum (CSR gather) -------------------------
// One warp per node, float2 lanes; overwrites agg (no zeroing needed).

__global__ void __launch_bounds__(256) k_agg(
    const float* __restrict__ h, const int* __restrict__ rowptr,
    const int* __restrict__ csr, float* __restrict__ agg, int n)
{
    int gw   = (blockIdx.x * blockDim.x + threadIdx.x) >> 5;
    int lane = threadIdx.x & 31;
    if (gw >= n) return;
    int beg = rowptr[gw], end = rowptr[gw + 1];
    float2 acc = make_float2(0.f, 0.f);
    int p = beg;
    for (; p + 4 <= end; p += 4) {
        int e0 = csr[p], e1 = csr[p + 1], e2 = csr[p + 2], e3 = csr[p + 3];
        float2 v0 = *(const float2*)&h[(size_t)e0 * 64 + lane * 2];
        float2 v1 = *(const float2*)&h[(size_t)e1 * 64 + lane * 2];
        float2 v2 = *(const float2*)&h[(size_t)e2 * 64 + lane * 2];
        float2 v3 = *(const float2*)&h[(size_t)e3 * 64 + lane * 2];
        acc.x += (v0.x + v1.x) + (v2.x + v3.x);
        acc.y += (v0.y + v1.y) + (v2.y + v3.y);
    }
    for (; p < end; ++p) {
        int e = csr[p];
        float2 v = *(const float2*)&h[(size_t)e * 64 + lane * 2];
        acc.x += v.x;
        acc.y += v.y;
    }
    *(float2*)&agg[(size_t)gw * 64 + lane * 2] = acc;
}

// ------------------------------- row GEMM ----------------------------------
// Y[nrows,64] = (relu?)( [X1 || X2] @ W + bias ), 64x64 tile, 256 threads,
// 4x4 microtile. K1, K2 multiples of 64.

template <int K1, int K2, bool RELU>
__global__ void __launch_bounds__(256) k_node_gemm(
    const float* __restrict__ X1, const float* __restrict__ X2,
    const float* __restrict__ W, const float* __restrict__ bias,
    float* __restrict__ Y, int nrows)
{
    __shared__ __align__(16) float xs[64][64];
    __shared__ __align__(16) float ws[64][64];
    const int t0  = blockIdx.x * 64;
    const int tid = threadIdx.x;
    const int tc  = tid & 15;
    const int tr  = tid >> 4;
    float acc[4][4];
#pragma unroll
    for (int r = 0; r < 4; ++r)
#pragma unroll
        for (int c = 0; c < 4; ++c) acc[r][c] = 0.f;

    const int K = K1 + K2;
    for (int k0 = 0; k0 < K; k0 += 64) {
        const float* Xsrc;
        int ld, koff;
        if (k0 < K1) { Xsrc = X1; ld = K1; koff = k0; }
        else         { Xsrc = X2; ld = K2; koff = k0 - K1; }
        for (int i = tid; i < 64 * 16; i += 256) {
            int row = i >> 4, c4 = (i & 15) * 4;
            float4 v = make_float4(0.f, 0.f, 0.f, 0.f);
            if (t0 + row < nrows)
                v = *(const float4*)&Xsrc[(size_t)(t0 + row) * ld + koff + c4];
            *(float4*)&xs[row][c4] = v;
        }
        for (int i = tid; i < 64 * 16; i += 256) {
            int k = i >> 4, c4 = (i & 15) * 4;
            *(float4*)&ws[k][c4] = *(const float4*)&W[(size_t)(k0 + k) * 64 + c4];
        }
        __syncthreads();
#pragma unroll
        for (int kq = 0; kq < 16; ++kq) {
#pragma unroll
            for (int kk = 0; kk < 4; ++kk) {
                float4 wv = *(const float4*)&ws[kq * 4 + kk][tc * 4];
#pragma unroll
                for (int r = 0; r < 4; ++r) {
                    float a = xs[tr * 4 + r][kq * 4 + kk];
                    acc[r][0] += a * wv.x;
                    acc[r][1] += a * wv.y;
                    acc[r][2] += a * wv.z;
                    acc[r][3] += a * wv.w;
                }
            }
        }
        __syncthreads();
    }
    float4 bv = *(const float4*)&bias[tc * 4];
#pragma unroll
    for (int r = 0; r < 4; ++r) {
        int row = t0 + tr * 4 + r;
        if (row < nrows) {
            float4 o;
            o.x = acc[r][0] + bv.x;
            o.y = acc[r][1] + bv.y;
            o.z = acc[r][2] + bv.z;
            o.w = acc[r][3] + bv.w;
            if (RELU) {
                o.x = fmaxf(o.x, 0.f); o.y = fmaxf(o.y, 0.f);
                o.z = fmaxf(o.z, 0.f); o.w = fmaxf(o.w, 0.f);
            }
            *(float4*)&Y[(size_t)row * 64 + tc * 4] = o;
        }
    }
}

// ------------------------- h0: thread per (e, u4) --------------------------

__global__ void __launch_bounds__(256) k_h0s(
    const float* __restrict__ ef, const float* __restrict__ W1b,
    const int* __restrict__ src, const float* __restrict__ P,
    float* __restrict__ h, int E)
{
    int i = blockIdx.x * blockDim.x + threadIdx.x;
    int e = i >> 4, u4 = (i & 15) * 4;
    if (e >= E) return;
    float4 acc = *(const float4*)&P[(size_t)src[e] * 64 + u4];  // P (has b1)
#pragma unroll 8
    for (int k = 0; k < 32; ++k) {
        float a = ef[(size_t)e * 32 + k];
        float4 w = *(const float4*)&W1b[k * 64 + u4];
        acc.x += a * w.x;
        acc.y += a * w.y;
        acc.z += a * w.z;
        acc.w += a * w.w;
    }
    acc.x = fmaxf(acc.x, 0.f);
    acc.y = fmaxf(acc.y, 0.f);
    acc.z = fmaxf(acc.z, 0.f);
    acc.w = fmaxf(acc.w, 0.f);
    *(float4*)&h[(size_t)e * 64 + u4] = acc;
}

// --------------------- fused message-passing step --------------------------
// Block handles tile [t0,t0+64) and mirror [t0+H,t0+H+64). Computes
// g = h @ Wu for BOTH tiles in registers, then
//   h[e1] = relu(A[src[e1]] - valid*g[e2] + h[e1])  (and symmetric e2).
// 512 threads, 2 blocks/SM; microtile 2 tiles x (2x4) = 16 accs.

__global__ void __launch_bounds__(512, 2) k_step(
    const float* __restrict__ Wu,
    const int* __restrict__ src, const int* __restrict__ dst,
    const float* __restrict__ A, float* __restrict__ h, int E, int H)
{
    __shared__ __align__(16) float ws[64][64];        // 16 KB  [k][col]
    __shared__ __align__(16) float hs[2][64][64];     // 32 KB  [half][row][k]
    const int t0  = blockIdx.x * 64;
    const int tid = threadIdx.x;
    const int tc  = tid & 15;   // 16 col-groups of 4
    const int tr  = tid >> 4;   // 32 row-pairs

    // hoist epilogue indices so the A-gathers issue without index latency
    const int eA = t0 + tr * 2;
    int s1a = 0, d1a = 0, s2a = 0, d2a = 0;
    int s1b = 0, d1b = 0, s2b = 0, d2b = 0;
    if (eA < H) {
        s1a = src[eA];     d1a = dst[eA];
        s2a = src[eA + H]; d2a = dst[eA + H];
        if (eA + 1 < H) {
            s1b = src[eA + 1];     d1b = dst[eA + 1];
            s2b = src[eA + 1 + H]; d2b = dst[eA + 1 + H];
        }
    }

    for (int i = tid; i < 64 * 16; i += 512) {
        int k = i >> 4, c4 = (i & 15) * 4;
        *(float4*)&ws[k][c4] = *(const float4*)&Wu[(size_t)k * 64 + c4];
    }
    for (int i = tid; i < 2 * 64 * 16; i += 512) {
        int half = i >> 10;                // 0 or 1
        int rem  = i & 1023;
        int row  = rem >> 4, c4 = (rem & 15) * 4;
        float4 v = make_float4(0.f, 0.f, 0.f, 0.f);
        if (t0 + row < H)
            v = *(const float4*)&h[(size_t)(t0 + row + half * H) * 64 + c4];
        *(float4*)&hs[half][row][c4] = v;
    }
    __syncthreads();

    float acc1[2][4], acc2[2][4];
#pragma unroll
    for (int r = 0; r < 2; ++r)
#pragma unroll
        for (int c = 0; c < 4; ++c) { acc1[r][c] = 0.f; acc2[r][c] = 0.f; }

#pragma unroll
    for (int kq = 0; kq < 16; ++kq) {
        float4 aq0[2], aq1[2];
#pragma unroll
        for (int r = 0; r < 2; ++r) {
            aq0[r] = *(const float4*)&hs[0][tr * 2 + r][kq * 4];
            aq1[r] = *(const float4*)&hs[1][tr * 2 + r][kq * 4];
        }
#pragma unroll
        for (int kk = 0; kk < 4; ++kk) {
            float4 wv = *(const float4*)&ws[kq * 4 + kk][tc * 4];
#pragma unroll
            for (int r = 0; r < 2; ++r) {
                float a0 = ((const float*)&aq0[r])[kk];
                float a1 = ((const float*)&aq1[r])[kk];
                acc1[r][0] += a0 * wv.x;
                acc1[r][1] += a0 * wv.y;
                acc1[r][2] += a0 * wv.z;
                acc1[r][3] += a0 * wv.w;
                acc2[r][0] += a1 * wv.x;
                acc2[r][1] += a1 * wv.y;
                acc2[r][2] += a1 * wv.z;
                acc2[r][3] += a1 * wv.w;
            }
        }
    }

#pragma unroll
    for (int r = 0; r < 2; ++r) {
        int i  = tr * 2 + r;
        int e1 = t0 + i;
        if (e1 < H) {
            int e2 = e1 + H;
            int s1 = r ? s1b : s1a;
            int d1 = r ? d1b : d1a;
            int s2 = r ? s2b : s2a;
            int d2 = r ? d2b : d2a;
            bool valid = (s2 == d1) && (d2 == s1);
            float4 A1 = *(const float4*)&A[(size_t)s1 * 64 + tc * 4];  // has bu
            float4 A2 = *(const float4*)&A[(size_t)s2 * 64 + tc * 4];
            float g1x = valid ? acc1[r][0] : 0.f, g1y = valid ? acc1[r][1] : 0.f;
            float g1z = valid ? acc1[r][2] : 0.f, g1w = valid ? acc1[r][3] : 0.f;
            float g2x = valid ? acc2[r][0] : 0.f, g2y = valid ? acc2[r][1] : 0.f;
            float g2z = valid ? acc2[r][2] : 0.f, g2w = valid ? acc2[r][3] : 0.f;
            float4 o1, o2;
            o1.x = fmaxf(A1.x - g2x + hs[0][i][tc * 4 + 0], 0.f);
            o1.y = fmaxf(A1.y - g2y + hs[0][i][tc * 4 + 1], 0.f);
            o1.z = fmaxf(A1.z - g2z + hs[0][i][tc * 4 + 2], 0.f);
            o1.w = fmaxf(A1.w - g2w + hs[0][i][tc * 4 + 3], 0.f);
            o2.x = fmaxf(A2.x - g1x + hs[1][i][tc * 4 + 0], 0.f);
            o2.y = fmaxf(A2.y - g1y + hs[1][i][tc * 4 + 1], 0.f);
            o2.z = fmaxf(A2.z - g1z + hs[1][i][tc * 4 + 2], 0.f);
            o2.w = fmaxf(A2.w - g1w + hs[1][i][tc * 4 + 3], 0.f);
            *(float4*)&h[(size_t)e1 * 64 + tc * 4] = o1;
            *(float4*)&h[(size_t)e2 * 64 + tc * 4] = o2;
        }
    }
}

// ---- local-memory pool pre-reservation (2 KB/thread frame) ----------------

__global__ void k_reserve(int n, int* out) {
    volatile float buf[512];
    for (int i = 0; i < n; ++i) buf[i] = (float)i;
    if (n > 1) *out = (int)buf[n - 2];
}

// ---------------- resolved device addresses of module globals ---------------

namespace {
struct DevPtrs {
    float *h, *agg, *A;
    int   *rowptr, *deg, *csr, *idum;
};

DevPtrs resolve_ptrs() {
    DevPtrs p{};
    cudaGetSymbolAddress((void**)&p.h,      g_h);
    cudaGetSymbolAddress((void**)&p.agg,    g_agg);
    cudaGetSymbolAddress((void**)&p.A,      g_A);
    cudaGetSymbolAddress((void**)&p.rowptr, g_rowptr);
    cudaGetSymbolAddress((void**)&p.deg,    g_deg);
    cudaGetSymbolAddress((void**)&p.csr,    g_csr);
    cudaGetSymbolAddress((void**)&p.idum,   g_idum);
    return p;
}

// --------- static-init warmup: force every lazy driver allocation ----------

struct DmpnnWarmup {
    DmpnnWarmup() {
        DevPtrs p = resolve_ptrs();         // context init + eager module load
        if (!p.h) return;
        k_zero_deg<<<1, 256>>>(p.deg, 0);
        k_hist<<<1, 256>>>(p.idum, p.deg, 0);
        k_scan<<<1, 1024>>>(p.deg, p.rowptr, 0);
        k_fill<<<1, 256>>>(p.idum, p.rowptr, p.deg, p.csr, 0);
        k_agg<<<1, 256>>>(p.h, p.rowptr, p.csr, p.agg, 0);
        k_h0s<<<1, 256>>>(p.agg, p.A, p.idum, p.A, p.h, 0);
        k_step<<<1, 512>>>(p.A, p.idum, p.idum, p.A, p.h, 0, 0);
        k_node_gemm<128, 0, false><<<1, 256>>>(p.agg, nullptr, p.A, p.A, p.agg, 0);
        k_node_gemm<64, 0, false><<<1, 256>>>(p.agg, nullptr, p.A, p.A, p.agg, 0);
        k_node_gemm<128, 64, true><<<1, 256>>>(p.agg, p.agg, p.A, p.A, p.agg, 0);
        k_reserve<<<1, 32>>>(0, p.idum);
        cudaDeviceSynchronize();            // outside kernel_launch: legal
        (void)cudaGetLastError();
    }
};
static DmpnnWarmup s_warmup;
}  // namespace

// ------------------------------- launcher ----------------------------------

extern "C" void kernel_launch(void* const* d_in, const int* in_sizes, int n_in,
                              void* d_out, int out_size)
{
    DevPtrs P = resolve_ptrs();   // true device addresses (capture-safe query)

    // order-agnostic binding by size rank (stable sort keeps src before dst)
    int order[16];
    for (int i = 0; i < n_in; ++i) order[i] = i;
    for (int i = 1; i < n_in; ++i) {
        int oi = order[i];
        long long si = in_sizes[oi];
        int j = i - 1;
        while (j >= 0 && (long long)in_sizes[order[j]] > si) {
            order[j + 1] = order[j];
            --j;
        }
        order[j + 1] = oi;
    }
    const float* b1 = (const float*)d_in[order[0]];
    const float* bu = (const float*)d_in[order[1]];
    const float* bf = (const float*)d_in[order[2]];
    const float* Wu = (const float*)d_in[order[3]];            // 64*64
    const float* W1 = (const float*)d_in[order[4]];            // 160*64
    const float* Wf = (const float*)d_in[order[5]];            // 192*64
    const int*   edge_src = (const int*)d_in[order[6]];        // E
    const int*   edge_dst = (const int*)d_in[order[7]];        // E
    const float* node_feature = (const float*)d_in[order[8]];  // N*128
    const float* edge_feature = (const float*)d_in[order[9]];  // E*32

    const int E = in_sizes[order[6]];
    const int H = E / 2;
    const int N = in_sizes[order[8]] / 128;

    const int ZB = (N + 255) / 256;
    const int EB = (E + 255) / 256;
    const int eu4Blocks   = (E * 16 + 255) / 256;
    const int nTileBlocks = (N + 63) / 64;
    const int stepBlocks  = (H + 63) / 64;
    const int aggBlocks   = (N * 32 + 255) / 256;

    // --- CSR over dst (shared by all 5 segment sums) ---
    k_zero_deg<<<ZB, 256>>>(P.deg, N);
    k_hist<<<EB, 256>>>(edge_dst, P.deg, E);
    k_scan<<<1, 1024>>>(P.deg, P.rowptr, N);
    k_zero_deg<<<ZB, 256>>>(P.deg, N);
    k_fill<<<EB, 256>>>(edge_dst, P.rowptr, P.deg, P.csr, E);

    // P = node @ W1[:128] + b1  -> g_A
    k_node_gemm<128, 0, false><<<nTileBlocks, 256>>>(node_feature, nullptr, W1, b1, P.A, N);
    // h0 = relu(P[src] + ef @ W1[128:])
    k_h0s<<<eu4Blocks, 256>>>(edge_feature, W1 + 128 * 64, edge_src, P.A, P.h, E);

    for (int step = 0; step < 4; ++step) {
        k_agg<<<aggBlocks, 256>>>(P.h, P.rowptr, P.csr, P.agg, N);
        k_node_gemm<64, 0, false><<<nTileBlocks, 256>>>(P.agg, nullptr, Wu, bu, P.A, N);
        k_step<<<stepBlocks, 512>>>(Wu, edge_src, edge_dst, P.A, P.h, E, H);
    }

    // out = relu([node || gather(h)] @ Wf + bf)
    k_agg<<<aggBlocks, 256>>>(P.h, P.rowptr, P.csr, P.agg, N);
    k_node_gemm<128, 64, true><<<nTileBlocks, 256>>>(
        node_feature, P.agg, Wf, bf, (float*)d_out, N);
}

// round 14
// speedup vs baseline: 1.1211x; 1.1211x over previous
#include <cuda_runtime.h>
#include <cuda_bf16.h>
#include <cstdint>

// ---------------------------------------------------------------------------
// DMPNN, round 14 = round 13 + missing <cstdint> (compile fix; theory untested):
//  (a) k_step prefetches gathered A rows via cp.async into dynamic smem
//      (epilogue A-gather latency hidden under the mainloop),
//  (b) last k_step skips the h store (dead after final scatter),
//  (c) agg zeroing fused into the A-GEMM (block zeroes rows it consumed).
// Structure:
//   P  = node @ W1[:128] + b1 ; h0 = relu(P[src] + ef @ W1[128:]) + red.v4
//   4x: A = agg @ Wu + bu (and zero agg rows) ;
//       k_step: mirror tile pair, g = h@Wu in regs,
//               h = relu(A[src] - valid*g[rev] + h); red.v4 into agg
//   out = relu([node || agg] @ Wf + bf)
// Known-good invariants: scalar FFMA only (f32x2 slower on sm_100a);
// 512 thr / 2 blocks/SM on k_step; red.v4 scatter (gather measured slower);
// cudaGetSymbolAddress for ALL device globals (ATS trap); static-init warmup.
// ---------------------------------------------------------------------------

#define EMAX 800000
#define NMAX 50000

__device__ float g_h[(size_t)EMAX * 64];     // edge hidden state
__device__ float g_agg[(size_t)NMAX * 64];   // segment sums
__device__ float g_A[(size_t)NMAX * 64];     // P, then A per step
__device__ int   g_idum[64];                 // warmup scratch

// ----------------------------- tiny utilities ------------------------------

__global__ void k_zero(float* __restrict__ p, int n4) {   // n4 = count of float4
    int i = blockIdx.x * blockDim.x + threadIdx.x;
    if (i < n4) ((float4*)p)[i] = make_float4(0.f, 0.f, 0.f, 0.f);
}

__device__ __forceinline__ void red_add_v4(float* p, float x, float y, float z, float w) {
    asm volatile("red.global.add.v4.f32 [%0], {%1, %2, %3, %4};"
                 :: "l"(p), "f"(x), "f"(y), "f"(z), "f"(w) : "memory");
}

__device__ __forceinline__ unsigned int smem_u32(const void* p) {
    unsigned int a;
    asm("{ .reg .u64 t; cvta.to.shared.u64 t, %1; cvt.u32.u64 %0, t; }"
        : "=r"(a) : "l"(p));
    return a;
}

__device__ __forceinline__ void cp_async16(unsigned int s, const void* g) {
    asm volatile("cp.async.cg.shared.global [%0], [%1], 16;" :: "r"(s), "l"(g));
}

// ------------------------------- row GEMM ----------------------------------
// Y[nrows,64] = (relu?)( [X1 || X2] @ W + bias ); if zeroX1 != nullptr the
// block zeroes the X1 rows it consumed (used with K1==64 only).

template <int K1, int K2, bool RELU>
__global__ void __launch_bounds__(256) k_node_gemm(
    const float* __restrict__ X1, const float* __restrict__ X2,
    const float* __restrict__ W, const float* __restrict__ bias,
    float* __restrict__ Y, int nrows, float* __restrict__ zeroX1)
{
    __shared__ __align__(16) float xs[64][64];
    __shared__ __align__(16) float ws[64][64];
    const int t0  = blockIdx.x * 64;
    const int tid = threadIdx.x;
    const int tc  = tid & 15;
    const int tr  = tid >> 4;
    float acc[4][4];
#pragma unroll
    for (int r = 0; r < 4; ++r)
#pragma unroll
        for (int c = 0; c < 4; ++c) acc[r][c] = 0.f;

    const int K = K1 + K2;
    for (int k0 = 0; k0 < K; k0 += 64) {
        const float* Xsrc;
        int ld, koff;
        if (k0 < K1) { Xsrc = X1; ld = K1; koff = k0; }
        else         { Xsrc = X2; ld = K2; koff = k0 - K1; }
        for (int i = tid; i < 64 * 16; i += 256) {
            int row = i >> 4, c4 = (i & 15) * 4;
            float4 v = make_float4(0.f, 0.f, 0.f, 0.f);
            if (t0 + row < nrows)
                v = *(const float4*)&Xsrc[(size_t)(t0 + row) * ld + koff + c4];
            *(float4*)&xs[row][c4] = v;
        }
        for (int i = tid; i < 64 * 16; i += 256) {
            int k = i >> 4, c4 = (i & 15) * 4;
            *(float4*)&ws[k][c4] = *(const float4*)&W[(size_t)(k0 + k) * 64 + c4];
        }
        __syncthreads();
        if (zeroX1 && k0 == 0) {   // rows now safely in smem: reset for scatter
            for (int i = tid; i < 64 * 16; i += 256) {
                int row = i >> 4, c4 = (i & 15) * 4;
                if (t0 + row < nrows)
                    *(float4*)&zeroX1[(size_t)(t0 + row) * K1 + c4] =
                        make_float4(0.f, 0.f, 0.f, 0.f);
            }
        }
#pragma unroll
        for (int kq = 0; kq < 16; ++kq) {
#pragma unroll
            for (int kk = 0; kk < 4; ++kk) {
                float4 wv = *(const float4*)&ws[kq * 4 + kk][tc * 4];
#pragma unroll
                for (int r = 0; r < 4; ++r) {
                    float a = xs[tr * 4 + r][kq * 4 + kk];
                    acc[r][0] += a * wv.x;
                    acc[r][1] += a * wv.y;
                    acc[r][2] += a * wv.z;
                    acc[r][3] += a * wv.w;
                }
            }
        }
        __syncthreads();
    }
    float4 bv = *(const float4*)&bias[tc * 4];
#pragma unroll
    for (int r = 0; r < 4; ++r) {
        int row = t0 + tr * 4 + r;
        if (row < nrows) {
            float4 o;
            o.x = acc[r][0] + bv.x;
            o.y = acc[r][1] + bv.y;
            o.z = acc[r][2] + bv.z;
            o.w = acc[r][3] + bv.w;
            if (RELU) {
                o.x = fmaxf(o.x, 0.f); o.y = fmaxf(o.y, 0.f);
                o.z = fmaxf(o.z, 0.f); o.w = fmaxf(o.w, 0.f);
            }
            *(float4*)&Y[(size_t)row * 64 + tc * 4] = o;
        }
    }
}

// ---------------- h0 (+ scatter): thread per (e, u4) -----------------------

__global__ void __launch_bounds__(256) k_h0s(
    const float* __restrict__ ef, const float* __restrict__ W1b,
    const int* __restrict__ src, const int* __restrict__ dst,
    const float* __restrict__ P, float* __restrict__ h,
    float* __restrict__ agg, int E)
{
    int i = blockIdx.x * blockDim.x + threadIdx.x;
    int e = i >> 4, u4 = (i & 15) * 4;
    if (e >= E) return;
    float4 acc = *(const float4*)&P[(size_t)src[e] * 64 + u4];  // P (has b1)
#pragma unroll 8
    for (int k = 0; k < 32; ++k) {
        float a = ef[(size_t)e * 32 + k];
        float4 w = *(const float4*)&W1b[k * 64 + u4];
        acc.x += a * w.x;
        acc.y += a * w.y;
        acc.z += a * w.z;
        acc.w += a * w.w;
    }
    acc.x = fmaxf(acc.x, 0.f);
    acc.y = fmaxf(acc.y, 0.f);
    acc.z = fmaxf(acc.z, 0.f);
    acc.w = fmaxf(acc.w, 0.f);
    *(float4*)&h[(size_t)e * 64 + u4] = acc;
    red_add_v4(&agg[(size_t)dst[e] * 64 + u4], acc.x, acc.y, acc.z, acc.w);
}

// --------------------- fused message-passing step --------------------------
// Tile pair [t0,t0+64) / [t0+H,t0+H+64). g = h@Wu for both tiles in regs;
//   h[e1] = relu(A[src[e1]] - valid*g[e2] + h[e1])  (and symmetric e2);
// stores h (unless storeH==0) and red.v4-scatters into agg.
// A rows for the whole block are cp.async-prefetched into dynamic smem so the
// epilogue gather is latency-free. 512 threads, 2 blocks/SM.

__global__ void __launch_bounds__(512, 2) k_step(
    const float* __restrict__ Wu,
    const int* __restrict__ src, const int* __restrict__ dst,
    const float* __restrict__ A, float* __restrict__ h,
    float* __restrict__ agg, int E, int H, int storeH)
{
    __shared__ __align__(16) float ws[64][64];        // 16 KB  [k][col]
    __shared__ __align__(16) float hs[2][64][64];     // 32 KB  [half][row][k]
    extern __shared__ __align__(16) float As[];       // 32 KB dyn: [128][64]
    const int t0  = blockIdx.x * 64;
    const int tid = threadIdx.x;
    const int tc  = tid & 15;   // 16 col-groups of 4
    const int tr  = tid >> 4;   // 32 row-pairs

    // ---- cp.async prefetch of gathered A rows (row r of 128, 64B segment) --
    {
        int r   = tid >> 2;            // 0..127
        int seg = tid & 3;             // 64-byte segment
        int lrow = (r < 64) ? r : (r - 64);
        bool ok = (t0 + lrow < H);
        if (ok) {
            int er   = (r < 64) ? (t0 + lrow) : (t0 + lrow + H);
            int srow = src[er];
            const float* gp = A + (size_t)srow * 64 + seg * 16;
            unsigned int sp = smem_u32(&As[r * 64 + seg * 16]);
            cp_async16(sp,      gp);
            cp_async16(sp + 16, gp + 4);
            cp_async16(sp + 32, gp + 8);
            cp_async16(sp + 48, gp + 12);
        }
        asm volatile("cp.async.commit_group;" ::: "memory");
    }

    // hoist epilogue indices (validity check + scatter destinations)
    const int eA = t0 + tr * 2;
    int s1a = 0, d1a = 0, s2a = 0, d2a = 0;
    int s1b = 0, d1b = 0, s2b = 0, d2b = 0;
    if (eA < H) {
        s1a = src[eA];     d1a = dst[eA];
        s2a = src[eA + H]; d2a = dst[eA + H];
        if (eA + 1 < H) {
            s1b = src[eA + 1];     d1b = dst[eA + 1];
            s2b = src[eA + 1 + H]; d2b = dst[eA + 1 + H];
        }
    }

    for (int i = tid; i < 64 * 16; i += 512) {
        int k = i >> 4, c4 = (i & 15) * 4;
        *(float4*)&ws[k][c4] = *(const float4*)&Wu[(size_t)k * 64 + c4];
    }
    for (int i = tid; i < 2 * 64 * 16; i += 512) {
        int half = i >> 10;                // 0 or 1
        int rem  = i & 1023;
        int row  = rem >> 4, c4 = (rem & 15) * 4;
        float4 v = make_float4(0.f, 0.f, 0.f, 0.f);
        if (t0 + row < H)
            v = *(const float4*)&h[(size_t)(t0 + row + half * H) * 64 + c4];
        *(float4*)&hs[half][row][c4] = v;
    }
    asm volatile("cp.async.wait_group 0;" ::: "memory");
    __syncthreads();

    float acc1[2][4], acc2[2][4];
#pragma unroll
    for (int r = 0; r < 2; ++r)
#pragma unroll
        for (int c = 0; c < 4; ++c) { acc1[r][c] = 0.f; acc2[r][c] = 0.f; }

#pragma unroll
    for (int kq = 0; kq < 16; ++kq) {
        float4 aq0[2], aq1[2];
#pragma unroll
        for (int r = 0; r < 2; ++r) {
            aq0[r] = *(const float4*)&hs[0][tr * 2 + r][kq * 4];
            aq1[r] = *(const float4*)&hs[1][tr * 2 + r][kq * 4];
        }
#pragma unroll
        for (int kk = 0; kk < 4; ++kk) {
            float4 wv = *(const float4*)&ws[kq * 4 + kk][tc * 4];
#pragma unroll
            for (int r = 0; r < 2; ++r) {
                float a0 = ((const float*)&aq0[r])[kk];
                float a1 = ((const float*)&aq1[r])[kk];
                acc1[r][0] += a0 * wv.x;
                acc1[r][1] += a0 * wv.y;
                acc1[r][2] += a0 * wv.z;
                acc1[r][3] += a0 * wv.w;
                acc2[r][0] += a1 * wv.x;
                acc2[r][1] += a1 * wv.y;
                acc2[r][2] += a1 * wv.z;
                acc2[r][3] += a1 * wv.w;
            }
        }
    }

#pragma unroll
    for (int r = 0; r < 2; ++r) {
        int i  = tr * 2 + r;
        int e1 = t0 + i;
        if (e1 < H) {
            int e2 = e1 + H;
            int s1 = r ? s1b : s1a;
            int d1 = r ? d1b : d1a;
            int s2 = r ? s2b : s2a;
            int d2 = r ? d2b : d2a;
            bool valid = (s2 == d1) && (d2 == s1);
            float4 A1 = *(const float4*)&As[i * 64 + tc * 4];         // A[s1]
            float4 A2 = *(const float4*)&As[(64 + i) * 64 + tc * 4];  // A[s2]
            float g1x = valid ? acc1[r][0] : 0.f, g1y = valid ? acc1[r][1] : 0.f;
            float g1z = valid ? acc1[r][2] : 0.f, g1w = valid ? acc1[r][3] : 0.f;
            float g2x = valid ? acc2[r][0] : 0.f, g2y = valid ? acc2[r][1] : 0.f;
            float g2z = valid ? acc2[r][2] : 0.f, g2w = valid ? acc2[r][3] : 0.f;
            float4 o1, o2;
            o1.x = fmaxf(A1.x - g2x + hs[0][i][tc * 4 + 0], 0.f);
            o1.y = fmaxf(A1.y - g2y + hs[0][i][tc * 4 + 1], 0.f);
            o1.z = fmaxf(A1.z - g2z + hs[0][i][tc * 4 + 2], 0.f);
            o1.w = fmaxf(A1.w - g2w + hs[0][i][tc * 4 + 3], 0.f);
            o2.x = fmaxf(A2.x - g1x + hs[1][i][tc * 4 + 0], 0.f);
            o2.y = fmaxf(A2.y - g1y + hs[1][i][tc * 4 + 1], 0.f);
            o2.z = fmaxf(A2.z - g1z + hs[1][i][tc * 4 + 2], 0.f);
            o2.w = fmaxf(A2.w - g1w + hs[1][i][tc * 4 + 3], 0.f);
            if (storeH) {
                *(float4*)&h[(size_t)e1 * 64 + tc * 4] = o1;
                *(float4*)&h[(size_t)e2 * 64 + tc * 4] = o2;
            }
            red_add_v4(&agg[(size_t)d1 * 64 + tc * 4], o1.x, o1.y, o1.z, o1.w);
            red_add_v4(&agg[(size_t)d2 * 64 + tc * 4], o2.x, o2.y, o2.z, o2.w);
        }
    }
}

// ---- local-memory pool pre-reservation (2 KB/thread frame) ----------------

__global__ void k_reserve(int n, int* out) {
    volatile float buf[512];
    for (int i = 0; i < n; ++i) buf[i] = (float)i;
    if (n > 1) *out = (int)buf[n - 2];
}

// ---------------- resolved device addresses of module globals ---------------

namespace {
struct DevPtrs {
    float *h, *agg, *A;
    int   *idum;
};

DevPtrs resolve_ptrs() {
    DevPtrs p{};
    cudaGetSymbolAddress((void**)&p.h,    g_h);
    cudaGetSymbolAddress((void**)&p.agg,  g_agg);
    cudaGetSymbolAddress((void**)&p.A,    g_A);
    cudaGetSymbolAddress((void**)&p.idum, g_idum);
    return p;
}

constexpr int KSTEP_DYNSMEM = 128 * 64 * 4;   // 32 KB for As

// --------- static-init warmup: force every lazy driver allocation ----------

struct DmpnnWarmup {
    DmpnnWarmup() {
        DevPtrs p = resolve_ptrs();         // context init + eager module load
        if (!p.h) return;
        cudaFuncSetAttribute(k_step, cudaFuncAttributeMaxDynamicSharedMemorySize,
                             KSTEP_DYNSMEM);
        k_zero<<<1, 256>>>(p.agg, 0);
        k_h0s<<<1, 256>>>(p.agg, p.A, p.idum, p.idum, p.A, p.h, p.agg, 0);
        k_step<<<1, 512, KSTEP_DYNSMEM>>>(p.A, p.idum, p.idum, p.A, p.h, p.agg, 0, 0, 1);
        k_node_gemm<128, 0, false><<<1, 256>>>(p.agg, nullptr, p.A, p.A, p.agg, 0, nullptr);
        k_node_gemm<64, 0, false><<<1, 256>>>(p.agg, nullptr, p.A, p.A, p.agg, 0, p.agg);
        k_node_gemm<128, 64, true><<<1, 256>>>(p.agg, p.agg, p.A, p.A, p.agg, 0, nullptr);
        k_reserve<<<1, 32>>>(0, p.idum);
        cudaDeviceSynchronize();            // outside kernel_launch: legal
        (void)cudaGetLastError();
    }
};
static DmpnnWarmup s_warmup;
}  // namespace

// ------------------------------- launcher ----------------------------------

extern "C" void kernel_launch(void* const* d_in, const int* in_sizes, int n_in,
                              void* d_out, int out_size)
{
    DevPtrs P = resolve_ptrs();   // true device addresses (capture-safe query)

    // order-agnostic binding by size rank (stable sort keeps src before dst)
    int order[16];
    for (int i = 0; i < n_in; ++i) order[i] = i;
    for (int i = 1; i < n_in; ++i) {
        int oi = order[i];
        long long si = in_sizes[oi];
        int j = i - 1;
        while (j >= 0 && (long long)in_sizes[order[j]] > si) {
            order[j + 1] = order[j];
            --j;
        }
        order[j + 1] = oi;
    }
    const float* b1 = (const float*)d_in[order[0]];
    const float* bu = (const float*)d_in[order[1]];
    const float* bf = (const float*)d_in[order[2]];
    const float* Wu = (const float*)d_in[order[3]];            // 64*64
    const float* W1 = (const float*)d_in[order[4]];            // 160*64
    const float* Wf = (const float*)d_in[order[5]];            // 192*64
    const int*   edge_src = (const int*)d_in[order[6]];        // E
    const int*   edge_dst = (const int*)d_in[order[7]];        // E
    const float* node_feature = (const float*)d_in[order[8]];  // N*128
    const float* edge_feature = (const float*)d_in[order[9]];  // E*32

    const int E = in_sizes[order[6]];
    const int H = E / 2;
    const int N = in_sizes[order[8]] / 128;

    const int aggZeroBlocks = (N * 16 + 255) / 256;        // float4 count = N*16
    const int eu4Blocks     = (E * 16 + 255) / 256;
    const int nTileBlocks   = (N + 63) / 64;
    const int stepBlocks    = (H + 63) / 64;

    // P = node @ W1[:128] + b1  -> g_A
    k_node_gemm<128, 0, false><<<nTileBlocks, 256>>>(
        node_feature, nullptr, W1, b1, P.A, N, nullptr);
    // h0 = relu(P[src] + ef @ W1[128:]), scatter into agg
    k_zero<<<aggZeroBlocks, 256>>>(P.agg, N * 16);
    k_h0s<<<eu4Blocks, 256>>>(edge_feature, W1 + 128 * 64, edge_src, edge_dst,
                              P.A, P.h, P.agg, E);

    for (int step = 0; step < 4; ++step) {
        // A = agg @ Wu + bu -> g_A; same kernel zeroes the consumed agg rows
        k_node_gemm<64, 0, false><<<nTileBlocks, 256>>>(
            P.agg, nullptr, Wu, bu, P.A, N, P.agg);
        // fused step: h update + scatter of new h (skip h store on last step)
        k_step<<<stepBlocks, 512, KSTEP_DYNSMEM>>>(
            Wu, edge_src, edge_dst, P.A, P.h, P.agg, E, H, step < 3 ? 1 : 0);
    }

    // out = relu([node || agg] @ Wf + bf)
    k_node_gemm<128, 64, true><<<nTileBlocks, 256>>>(
        node_feature, P.agg, Wf, bf, (float*)d_out, N, nullptr);
}

// round 15
// speedup vs baseline: 1.3168x; 1.1746x over previous
#include <cuda_runtime.h>
#include <cuda_bf16.h>
#include <cstdint>

// ---------------------------------------------------------------------------
// DMPNN, round 15 = R11 k_step (best, 1443us) + last-step h-store skip +
// agg-zeroing fused into A-GEMM + h0 rewritten as a tiled GEMM
// (old k_h0s was thread-per-(e,u4): ~6.8 GB of redundant L1 traffic).
// Structure:
//   P  = node @ W1[:128] + b1
//   h0 = relu(P[src] + ef @ W1[128:]) tile-GEMM; red.v4 scatter into agg
//   4x: A = agg @ Wu + bu (same kernel zeroes consumed agg rows)
//       k_step: mirror tile pair, g = h@Wu in regs,
//               h = relu(A[src] - valid*g[rev] + h); store h (not last);
//               red.v4 into agg
//   out = relu([node || agg] @ Wf + bf)
// Invariants: scalar FFMA only (f32x2 slower on sm_100a); 512thr/2blk-SM
// k_step; red.v4 scatter (CSR gather measured slower); cp.async A-prefetch
// measured slower (R14) — direct epilogue gather; cudaGetSymbolAddress for
// ALL device globals (ATS trap); static-init warmup for lazy driver allocs.
// ---------------------------------------------------------------------------

#define EMAX 800000
#define NMAX 50000

__device__ float g_h[(size_t)EMAX * 64];     // edge hidden state
__device__ float g_agg[(size_t)NMAX * 64];   // segment sums
__device__ float g_A[(size_t)NMAX * 64];     // P, then A per step
__device__ int   g_idum[64];                 // warmup scratch

// ----------------------------- tiny utilities ------------------------------

__global__ void k_zero(float* __restrict__ p, int n4) {   // n4 = count of float4
    int i = blockIdx.x * blockDim.x + threadIdx.x;
    if (i < n4) ((float4*)p)[i] = make_float4(0.f, 0.f, 0.f, 0.f);
}

__device__ __forceinline__ void red_add_v4(float* p, float x, float y, float z, float w) {
    asm volatile("red.global.add.v4.f32 [%0], {%1, %2, %3, %4};"
                 :: "l"(p), "f"(x), "f"(y), "f"(z), "f"(w) : "memory");
}

// ------------------------------- row GEMM ----------------------------------
// Y[nrows,64] = (relu?)( [X1 || X2] @ W + bias ); if zeroX1 != nullptr the
// block zeroes the X1 rows it consumed (used with K1==64 only; rows are
// block-exclusive so this is race-free).

template <int K1, int K2, bool RELU>
__global__ void __launch_bounds__(256) k_node_gemm(
    const float* __restrict__ X1, const float* __restrict__ X2,
    const float* __restrict__ W, const float* __restrict__ bias,
    float* __restrict__ Y, int nrows, float* __restrict__ zeroX1)
{
    __shared__ __align__(16) float xs[64][64];
    __shared__ __align__(16) float ws[64][64];
    const int t0  = blockIdx.x * 64;
    const int tid = threadIdx.x;
    const int tc  = tid & 15;
    const int tr  = tid >> 4;
    float acc[4][4];
#pragma unroll
    for (int r = 0; r < 4; ++r)
#pragma unroll
        for (int c = 0; c < 4; ++c) acc[r][c] = 0.f;

    const int K = K1 + K2;
    for (int k0 = 0; k0 < K; k0 += 64) {
        const float* Xsrc;
        int ld, koff;
        if (k0 < K1) { Xsrc = X1; ld = K1; koff = k0; }
        else         { Xsrc = X2; ld = K2; koff = k0 - K1; }
        for (int i = tid; i < 64 * 16; i += 256) {
            int row = i >> 4, c4 = (i & 15) * 4;
            float4 v = make_float4(0.f, 0.f, 0.f, 0.f);
            if (t0 + row < nrows)
                v = *(const float4*)&Xsrc[(size_t)(t0 + row) * ld + koff + c4];
            *(float4*)&xs[row][c4] = v;
        }
        for (int i = tid; i < 64 * 16; i += 256) {
            int k = i >> 4, c4 = (i & 15) * 4;
            *(float4*)&ws[k][c4] = *(const float4*)&W[(size_t)(k0 + k) * 64 + c4];
        }
        __syncthreads();
        if (zeroX1 && k0 == 0) {   // rows now safely in smem: reset for scatter
            for (int i = tid; i < 64 * 16; i += 256) {
                int row = i >> 4, c4 = (i & 15) * 4;
                if (t0 + row < nrows)
                    *(float4*)&zeroX1[(size_t)(t0 + row) * K1 + c4] =
                        make_float4(0.f, 0.f, 0.f, 0.f);
            }
        }
#pragma unroll
        for (int kq = 0; kq < 16; ++kq) {
#pragma unroll
            for (int kk = 0; kk < 4; ++kk) {
                float4 wv = *(const float4*)&ws[kq * 4 + kk][tc * 4];
#pragma unroll
                for (int r = 0; r < 4; ++r) {
                    float a = xs[tr * 4 + r][kq * 4 + kk];
                    acc[r][0] += a * wv.x;
                    acc[r][1] += a * wv.y;
                    acc[r][2] += a * wv.z;
                    acc[r][3] += a * wv.w;
                }
            }
        }
        __syncthreads();
    }
    float4 bv = *(const float4*)&bias[tc * 4];
#pragma unroll
    for (int r = 0; r < 4; ++r) {
        int row = t0 + tr * 4 + r;
        if (row < nrows) {
            float4 o;
            o.x = acc[r][0] + bv.x;
            o.y = acc[r][1] + bv.y;
            o.z = acc[r][2] + bv.z;
            o.w = acc[r][3] + bv.w;
            if (RELU) {
                o.x = fmaxf(o.x, 0.f); o.y = fmaxf(o.y, 0.f);
                o.z = fmaxf(o.z, 0.f); o.w = fmaxf(o.w, 0.f);
            }
            *(float4*)&Y[(size_t)row * 64 + tc * 4] = o;
        }
    }
}

// ---------------- h0 tile-GEMM (+ gather P, scatter agg) -------------------
// 64-edge tile: h[e] = relu(P[src[e]] + ef[e] @ W1b); red.v4 into agg[dst[e]].
// 256 threads, 4x4 microtile. ef/W1b staged in smem (kills the old kernel's
// ~6.8 GB of redundant L1 traffic).

__global__ void __launch_bounds__(256) k_h0g(
    const float* __restrict__ ef, const float* __restrict__ W1b,
    const int* __restrict__ src, const int* __restrict__ dst,
    const float* __restrict__ P, float* __restrict__ h,
    float* __restrict__ agg, int E)
{
    __shared__ __align__(16) float efs[64][32];   // 8 KB
    __shared__ __align__(16) float ws[32][64];    // 8 KB
    const int t0  = blockIdx.x * 64;
    const int tid = threadIdx.x;
    const int tc  = tid & 15;
    const int tr  = tid >> 4;

    for (int i = tid; i < 32 * 16; i += 256) {
        int k = i >> 4, c4 = (i & 15) * 4;
        *(float4*)&ws[k][c4] = *(const float4*)&W1b[(size_t)k * 64 + c4];
    }
    for (int i = tid; i < 64 * 8; i += 256) {
        int row = i >> 3, c4 = (i & 7) * 4;
        float4 v = make_float4(0.f, 0.f, 0.f, 0.f);
        if (t0 + row < E) v = *(const float4*)&ef[(size_t)(t0 + row) * 32 + c4];
        *(float4*)&efs[row][c4] = v;
    }
    __syncthreads();

    float acc[4][4];
#pragma unroll
    for (int r = 0; r < 4; ++r)
#pragma unroll
        for (int c = 0; c < 4; ++c) acc[r][c] = 0.f;

#pragma unroll
    for (int kq = 0; kq < 8; ++kq) {
        float4 aq[4];
#pragma unroll
        for (int r = 0; r < 4; ++r)
            aq[r] = *(const float4*)&efs[tr * 4 + r][kq * 4];
#pragma unroll
        for (int kk = 0; kk < 4; ++kk) {
            float4 wv = *(const float4*)&ws[kq * 4 + kk][tc * 4];
#pragma unroll
            for (int r = 0; r < 4; ++r) {
                float a = ((const float*)&aq[r])[kk];
                acc[r][0] += a * wv.x;
                acc[r][1] += a * wv.y;
                acc[r][2] += a * wv.z;
                acc[r][3] += a * wv.w;
            }
        }
    }

#pragma unroll
    for (int r = 0; r < 4; ++r) {
        int e = t0 + tr * 4 + r;
        if (e < E) {
            int s = src[e], d = dst[e];
            float4 pv = *(const float4*)&P[(size_t)s * 64 + tc * 4];  // has b1
            float4 o;
            o.x = fmaxf(acc[r][0] + pv.x, 0.f);
            o.y = fmaxf(acc[r][1] + pv.y, 0.f);
            o.z = fmaxf(acc[r][2] + pv.z, 0.f);
            o.w = fmaxf(acc[r][3] + pv.w, 0.f);
            *(float4*)&h[(size_t)e * 64 + tc * 4] = o;
            red_add_v4(&agg[(size_t)d * 64 + tc * 4], o.x, o.y, o.z, o.w);
        }
    }
}

// --------------------- fused message-passing step --------------------------
// Tile pair [t0,t0+64) / [t0+H,t0+H+64). g = h@Wu for both tiles in regs;
//   h[e1] = relu(A[src[e1]] - valid*g[e2] + h[e1])  (and symmetric e2);
// stores h (unless storeH==0) and red.v4-scatters into agg.
// 512 threads, 2 blocks/SM; microtile 2 tiles x (2x4) = 16 accs.

__global__ void __launch_bounds__(512, 2) k_step(
    const float* __restrict__ Wu,
    const int* __restrict__ src, const int* __restrict__ dst,
    const float* __restrict__ A, float* __restrict__ h,
    float* __restrict__ agg, int E, int H, int storeH)
{
    __shared__ __align__(16) float ws[64][64];        // 16 KB  [k][col]
    __shared__ __align__(16) float hs[2][64][64];     // 32 KB  [half][row][k]
    const int t0  = blockIdx.x * 64;
    const int tid = threadIdx.x;
    const int tc  = tid & 15;   // 16 col-groups of 4
    const int tr  = tid >> 4;   // 32 row-pairs

    // hoist epilogue indices so the A-gathers issue without index latency
    const int eA = t0 + tr * 2;
    int s1a = 0, d1a = 0, s2a = 0, d2a = 0;
    int s1b = 0, d1b = 0, s2b = 0, d2b = 0;
    if (eA < H) {
        s1a = src[eA];     d1a = dst[eA];
        s2a = src[eA + H]; d2a = dst[eA + H];
        if (eA + 1 < H) {
            s1b = src[eA + 1];     d1b = dst[eA + 1];
            s2b = src[eA + 1 + H]; d2b = dst[eA + 1 + H];
        }
    }

    for (int i = tid; i < 64 * 16; i += 512) {
        int k = i >> 4, c4 = (i & 15) * 4;
        *(float4*)&ws[k][c4] = *(const float4*)&Wu[(size_t)k * 64 + c4];
    }
    for (int i = tid; i < 2 * 64 * 16; i += 512) {
        int half = i >> 10;                // 0 or 1
        int rem  = i & 1023;
        int row  = rem >> 4, c4 = (rem & 15) * 4;
        float4 v = make_float4(0.f, 0.f, 0.f, 0.f);
        if (t0 + row < H)
            v = *(const float4*)&h[(size_t)(t0 + row + half * H) * 64 + c4];
        *(float4*)&hs[half][row][c4] = v;
    }
    __syncthreads();

    float acc1[2][4], acc2[2][4];
#pragma unroll
    for (int r = 0; r < 2; ++r)
#pragma unroll
        for (int c = 0; c < 4; ++c) { acc1[r][c] = 0.f; acc2[r][c] = 0.f; }

#pragma unroll
    for (int kq = 0; kq < 16; ++kq) {
        float4 aq0[2], aq1[2];
#pragma unroll
        for (int r = 0; r < 2; ++r) {
            aq0[r] = *(const float4*)&hs[0][tr * 2 + r][kq * 4];
            aq1[r] = *(const float4*)&hs[1][tr * 2 + r][kq * 4];
        }
#pragma unroll
        for (int kk = 0; kk < 4; ++kk) {
            float4 wv = *(const float4*)&ws[kq * 4 + kk][tc * 4];
#pragma unroll
            for (int r = 0; r < 2; ++r) {
                float a0 = ((const float*)&aq0[r])[kk];
                float a1 = ((const float*)&aq1[r])[kk];
                acc1[r][0] += a0 * wv.x;
                acc1[r][1] += a0 * wv.y;
                acc1[r][2] += a0 * wv.z;
                acc1[r][3] += a0 * wv.w;
                acc2[r][0] += a1 * wv.x;
                acc2[r][1] += a1 * wv.y;
                acc2[r][2] += a1 * wv.z;
                acc2[r][3] += a1 * wv.w;
            }
        }
    }

#pragma unroll
    for (int r = 0; r < 2; ++r) {
        int i  = tr * 2 + r;
        int e1 = t0 + i;
        if (e1 < H) {
            int e2 = e1 + H;
            int s1 = r ? s1b : s1a;
            int d1 = r ? d1b : d1a;
            int s2 = r ? s2b : s2a;
            int d2 = r ? d2b : d2a;
            bool valid = (s2 == d1) && (d2 == s1);
            float4 A1 = *(const float4*)&A[(size_t)s1 * 64 + tc * 4];  // has bu
            float4 A2 = *(const float4*)&A[(size_t)s2 * 64 + tc * 4];
            float g1x = valid ? acc1[r][0] : 0.f, g1y = valid ? acc1[r][1] : 0.f;
            float g1z = valid ? acc1[r][2] : 0.f, g1w = valid ? acc1[r][3] : 0.f;
            float g2x = valid ? acc2[r][0] : 0.f, g2y = valid ? acc2[r][1] : 0.f;
            float g2z = valid ? acc2[r][2] : 0.f, g2w = valid ? acc2[r][3] : 0.f;
            float4 o1, o2;
            o1.x = fmaxf(A1.x - g2x + hs[0][i][tc * 4 + 0], 0.f);
            o1.y = fmaxf(A1.y - g2y + hs[0][i][tc * 4 + 1], 0.f);
            o1.z = fmaxf(A1.z - g2z + hs[0][i][tc * 4 + 2], 0.f);
            o1.w = fmaxf(A1.w - g2w + hs[0][i][tc * 4 + 3], 0.f);
            o2.x = fmaxf(A2.x - g1x + hs[1][i][tc * 4 + 0], 0.f);
            o2.y = fmaxf(A2.y - g1y + hs[1][i][tc * 4 + 1], 0.f);
            o2.z = fmaxf(A2.z - g1z + hs[1][i][tc * 4 + 2], 0.f);
            o2.w = fmaxf(A2.w - g1w + hs[1][i][tc * 4 + 3], 0.f);
            if (storeH) {
                *(float4*)&h[(size_t)e1 * 64 + tc * 4] = o1;
                *(float4*)&h[(size_t)e2 * 64 + tc * 4] = o2;
            }
            red_add_v4(&agg[(size_t)d1 * 64 + tc * 4], o1.x, o1.y, o1.z, o1.w);
            red_add_v4(&agg[(size_t)d2 * 64 + tc * 4], o2.x, o2.y, o2.z, o2.w);
        }
    }
}

// ---- local-memory pool pre-reservation (2 KB/thread frame) ----------------

__global__ void k_reserve(int n, int* out) {
    volatile float buf[512];
    for (int i = 0; i < n; ++i) buf[i] = (float)i;
    if (n > 1) *out = (int)buf[n - 2];
}

// ---------------- resolved device addresses of module globals ---------------

namespace {
struct DevPtrs {
    float *h, *agg, *A;
    int   *idum;
};

DevPtrs resolve_ptrs() {
    DevPtrs p{};
    cudaGetSymbolAddress((void**)&p.h,    g_h);
    cudaGetSymbolAddress((void**)&p.agg,  g_agg);
    cudaGetSymbolAddress((void**)&p.A,    g_A);
    cudaGetSymbolAddress((void**)&p.idum, g_idum);
    return p;
}

// --------- static-init warmup: force every lazy driver allocation ----------

struct DmpnnWarmup {
    DmpnnWarmup() {
        DevPtrs p = resolve_ptrs();         // context init + eager module load
        if (!p.h) return;
        k_zero<<<1, 256>>>(p.agg, 0);
        k_h0g<<<1, 256>>>(p.agg, p.A, p.idum, p.idum, p.A, p.h, p.agg, 0);
        k_step<<<1, 512>>>(p.A, p.idum, p.idum, p.A, p.h, p.agg, 0, 0, 1);
        k_node_gemm<128, 0, false><<<1, 256>>>(p.agg, nullptr, p.A, p.A, p.agg, 0, nullptr);
        k_node_gemm<64, 0, false><<<1, 256>>>(p.agg, nullptr, p.A, p.A, p.agg, 0, p.agg);
        k_node_gemm<128, 64, true><<<1, 256>>>(p.agg, p.agg, p.A, p.A, p.agg, 0, nullptr);
        k_reserve<<<1, 32>>>(0, p.idum);
        cudaDeviceSynchronize();            // outside kernel_launch: legal
        (void)cudaGetLastError();
    }
};
static DmpnnWarmup s_warmup;
}  // namespace

// ------------------------------- launcher ----------------------------------

extern "C" void kernel_launch(void* const* d_in, const int* in_sizes, int n_in,
                              void* d_out, int out_size)
{
    DevPtrs P = resolve_ptrs();   // true device addresses (capture-safe query)

    // order-agnostic binding by size rank (stable sort keeps src before dst)
    int order[16];
    for (int i = 0; i < n_in; ++i) order[i] = i;
    for (int i = 1; i < n_in; ++i) {
        int oi = order[i];
        long long si = in_sizes[oi];
        int j = i - 1;
        while (j >= 0 && (long long)in_sizes[order[j]] > si) {
            order[j + 1] = order[j];
            --j;
        }
        order[j + 1] = oi;
    }
    const float* b1 = (const float*)d_in[order[0]];
    const float* bu = (const float*)d_in[order[1]];
    const float* bf = (const float*)d_in[order[2]];
    const float* Wu = (const float*)d_in[order[3]];            // 64*64
    const float* W1 = (const float*)d_in[order[4]];            // 160*64
    const float* Wf = (const float*)d_in[order[5]];            // 192*64
    const int*   edge_src = (const int*)d_in[order[6]];        // E
    const int*   edge_dst = (const int*)d_in[order[7]];        // E
    const float* node_feature = (const float*)d_in[order[8]];  // N*128
    const float* edge_feature = (const float*)d_in[order[9]];  // E*32

    const int E = in_sizes[order[6]];
    const int H = E / 2;
    const int N = in_sizes[order[8]] / 128;

    const int aggZeroBlocks = (N * 16 + 255) / 256;        // float4 count = N*16
    const int nTileBlocks   = (N + 63) / 64;
    const int eTileBlocks   = (E + 63) / 64;
    const int stepBlocks    = (H + 63) / 64;

    // P = node @ W1[:128] + b1  -> g_A
    k_node_gemm<128, 0, false><<<nTileBlocks, 256>>>(
        node_feature, nullptr, W1, b1, P.A, N, nullptr);
    // h0 = relu(P[src] + ef @ W1[128:]) tile-GEMM, scatter into agg
    k_zero<<<aggZeroBlocks, 256>>>(P.agg, N * 16);
    k_h0g<<<eTileBlocks, 256>>>(edge_feature, W1 + 128 * 64, edge_src, edge_dst,
                                P.A, P.h, P.agg, E);

    for (int step = 0; step < 4; ++step) {
        // A = agg @ Wu + bu -> g_A; same kernel zeroes the consumed agg rows
        k_node_gemm<64, 0, false><<<nTileBlocks, 256>>>(
            P.agg, nullptr, Wu, bu, P.A, N, P.agg);
        // fused step: h update + scatter of new h (skip h store on last step)
        k_step<<<stepBlocks, 512>>>(
            Wu, edge_src, edge_dst, P.A, P.h, P.agg, E, H, step < 3 ? 1 : 0);
    }

    // out = relu([node || agg] @ Wf + bf)
    k_node_gemm<128, 64, true><<<nTileBlocks, 256>>>(
        node_feature, P.agg, Wf, bf, (float*)d_out, N, nullptr);
}